// round 16
// baseline (speedup 1.0000x reference)
#include <cuda_runtime.h>
#include <cuda_fp16.h>
#include <cstdint>

#define NB 16
#define NC 512
#define NN 1024
#define NH 8
#define ND 64
#define LOG2E 1.4426950408889634f

// ---------------- scratch (device globals; allocation-free) ----------------
__device__ __align__(16) __half g_qh[(size_t)NB*NC*NN];
__device__ __align__(16) __half g_kh[(size_t)NB*NC*NN];   // scaled by log2e
__device__ __align__(16) __half g_vh[(size_t)NB*NC*NN];
__device__ __align__(16) __half g_xh[(size_t)NB*NC*NN];
__device__ __align__(16) __half g_wh[(size_t)3*NC*NC];    // Wk segment scaled by log2e
__device__ __align__(16) __half g_rh2[8*64*32];           // rel_h * log2e, [h][d][hc]
__device__ __align__(16) __half g_rw2[8*64*32];           // rel_w * log2e, [h][d][w]
__device__ __align__(16) float  g_abc[512];               // rel^T bq * log2e
__device__ __align__(16) float  g_ab[(size_t)NB*512*NN];  // rows: 0..255 A(h*32+hc), 256..511 B(h*32+w)

// ---------------- helpers ----------------
__device__ __forceinline__ void cp16(uint32_t dst, const void* src){
    asm volatile("cp.async.cg.shared.global [%0], [%1], 16;" :: "r"(dst), "l"(src));
}
__device__ __forceinline__ void cp_commit(){ asm volatile("cp.async.commit_group;"); }
template<int N> __device__ __forceinline__ void cp_wait(){
    asm volatile("cp.async.wait_group %0;" :: "n"(N));
}
__device__ __forceinline__ void ldsm4(uint32_t r[4], uint32_t a){
    asm volatile("ldmatrix.sync.aligned.m8n8.x4.shared.b16 {%0,%1,%2,%3},[%4];"
        : "=r"(r[0]),"=r"(r[1]),"=r"(r[2]),"=r"(r[3]) : "r"(a));
}
__device__ __forceinline__ void ldsm4t(uint32_t r[4], uint32_t a){
    asm volatile("ldmatrix.sync.aligned.m8n8.x4.trans.shared.b16 {%0,%1,%2,%3},[%4];"
        : "=r"(r[0]),"=r"(r[1]),"=r"(r[2]),"=r"(r[3]) : "r"(a));
}
__device__ __forceinline__ void ldsm2t(uint32_t r[2], uint32_t a){
    asm volatile("ldmatrix.sync.aligned.m8n8.x2.trans.shared.b16 {%0,%1},[%2];"
        : "=r"(r[0]),"=r"(r[1]) : "r"(a));
}
__device__ __forceinline__ void ldsm2(uint32_t r[2], uint32_t a){
    asm volatile("ldmatrix.sync.aligned.m8n8.x2.shared.b16 {%0,%1},[%2];"
        : "=r"(r[0]),"=r"(r[1]) : "r"(a));
}
__device__ __forceinline__ void mma_f16(float* c, const uint32_t* a, const uint32_t* b){
    asm volatile("mma.sync.aligned.m16n8k16.row.col.f32.f16.f16.f32 "
        "{%0,%1,%2,%3},{%4,%5,%6,%7},{%8,%9},{%0,%1,%2,%3};"
        : "+f"(c[0]),"+f"(c[1]),"+f"(c[2]),"+f"(c[3])
        : "r"(a[0]),"r"(a[1]),"r"(a[2]),"r"(a[3]),"r"(b[0]),"r"(b[1]));
}
__device__ __forceinline__ uint32_t packh2(float x, float y){
    __half2 t = __floats2half2_rn(x, y);
    return *reinterpret_cast<uint32_t*>(&t);
}
__device__ __forceinline__ float ex2f(float x){
    float y; asm("ex2.approx.ftz.f32 %0,%1;" : "=f"(y) : "f"(x)); return y;
}

// ---------------- fused convert fp32 -> fp16 (x + Wq + Wk*log2e + Wv) ----------------
#define X4 2097152
#define W4 65536
__global__ void cvt_all_kernel(const float* __restrict__ x,
                               const float* __restrict__ Wq,
                               const float* __restrict__ Wk,
                               const float* __restrict__ Wv){
    int i = blockIdx.x * blockDim.x + threadIdx.x;
    const float* src; __half* dst; float sc = 1.f; int li;
    if (i < X4){ src = x; dst = g_xh; li = i; }
    else {
        int j = i - X4;
        int seg = j / W4; li = j - seg*W4;
        src = (seg==0) ? Wq : (seg==1) ? Wk : Wv;
        dst = g_wh + (size_t)seg*W4*4;
        if (seg == 1) sc = LOG2E;
    }
    float4 v = reinterpret_cast<const float4*>(src)[li];
    __half2* d2 = reinterpret_cast<__half2*>(dst + (size_t)4*li);
    d2[0] = __floats2half2_rn(v.x*sc, v.y*sc);
    d2[1] = __floats2half2_rn(v.z*sc, v.w*sc);
}

// rel -> fp16 scaled, plus abc[row] = rel^T bq * log2e
__global__ void relabc_kernel(const float* __restrict__ rel_h,
                              const float* __restrict__ rel_w,
                              const float* __restrict__ bq){
    int idx = blockIdx.x * blockDim.x + threadIdx.x;
    if (idx < 16384){
        g_rh2[idx] = __float2half(rel_h[idx]*LOG2E);
        g_rw2[idx] = __float2half(rel_w[idx]*LOG2E);
    } else if (idx < 16896){
        int row = idx - 16384;
        int sel = row >> 8, rr = row & 255;
        int h = rr >> 5, c = rr & 31;
        const float* rel = sel ? rel_w : rel_h;
        float acc = 0.f;
        #pragma unroll 8
        for (int d = 0; d < 64; d++)
            acc += rel[(h*64 + d)*32 + c] * bq[h*64 + d];
        g_abc[row] = acc * LOG2E;
    }
}

// ---------------- QKV GEMM (unchanged R14) ----------------
__global__ __launch_bounds__(256) void qkv_mma_kernel(
    const float* __restrict__ bq, const float* __restrict__ bk,
    const float* __restrict__ bv)
{
    extern __shared__ uint4 smemraw[];
    const uint32_t sbase = (uint32_t)__cvta_generic_to_shared(smemraw);
    const int tid = threadIdx.x, lane = tid & 31, warp = tid >> 5;
    const int wm = warp >> 2, wn = warp & 3;
    const int which = blockIdx.z % 3;
    const int b = blockIdx.z / 3;
    const int oT = blockIdx.y * 128, nT = blockIdx.x * 128;

    const __half* Wh = g_wh + (size_t)which*NC*NC;
    const __half* Xh = g_xh + (size_t)b*NC*NN;
    const float* bias = (which==0) ? bq : (which==1) ? bk : bv;
    __half* Oh = (which==0) ? g_qh : (which==1) ? g_kh : g_vh;
    const float bsc = (which==1) ? LOG2E : 1.f;

    auto aAddr = [&](int buf,int row,int u)->uint32_t{
        return sbase + (uint32_t)(buf*512 + row*4 + (u ^ ((row>>1)&3)))*16u; };
    auto bAddr = [&](int buf,int row,int u)->uint32_t{
        return sbase + (uint32_t)(1024 + buf*512 + row*16 + (u ^ (row&7)))*16u; };

    auto issue = [&](int ct, int buf){
        #pragma unroll
        for (int s = 0; s < 2; s++){
            int idx = tid + (s<<8); int row = idx >> 2, u = idx & 3;
            cp16(aAddr(buf,row,u), Wh + (size_t)(oT+row)*NC + ct + u*8);
        }
        #pragma unroll
        for (int s = 0; s < 2; s++){
            int idx = tid + (s<<8); int row = idx >> 4, u = idx & 15;
            cp16(bAddr(buf,row,u), Xh + (size_t)(ct+row)*NN + nT + u*8);
        }
    };

    float C[4][4][4];
    #pragma unroll
    for (int a=0;a<4;a++)
        #pragma unroll
        for (int bb=0;bb<4;bb++)
            #pragma unroll
            for (int c=0;c<4;c++) C[a][bb][c]=0.f;

    issue(0, 0); cp_commit();
    for (int it = 0; it < 16; it++){
        if (it < 15){ issue((it+1)*32, (it+1)&1); cp_commit(); cp_wait<1>(); }
        else        { cp_wait<0>(); }
        __syncthreads();
        int buf = it & 1;
        #pragma unroll
        for (int k16 = 0; k16 < 2; k16++){
            int kk = k16 << 4;
            uint32_t ah[4][4], bh[4][2];
            #pragma unroll
            for (int mi = 0; mi < 4; mi++){
                int row = wm*64 + mi*16 + (lane & 15);
                ldsm4(ah[mi], aAddr(buf,row,(kk>>3)+(lane>>4)));
            }
            #pragma unroll
            for (int ni = 0; ni < 4; ni++)
                ldsm2t(bh[ni], bAddr(buf, kk + (lane & 15), wn*4 + ni));
            #pragma unroll
            for (int mi = 0; mi < 4; mi++)
                #pragma unroll
                for (int ni = 0; ni < 4; ni++)
                    mma_f16(C[mi][ni], ah[mi], bh[ni]);
        }
        __syncthreads();
    }
    #pragma unroll
    for (int mi = 0; mi < 4; mi++){
        int r0 = oT + wm*64 + mi*16 + (lane >> 2);
        float bi0 = bias[r0]*bsc, bi1 = bias[r0 + 8]*bsc;
        #pragma unroll
        for (int ni = 0; ni < 4; ni++){
            int c0 = nT + wn*32 + ni*8 + (lane & 3)*2;
            size_t o0 = ((size_t)b*NC + r0)*NN + c0;
            *reinterpret_cast<__half2*>(Oh + o0) =
                __floats2half2_rn(C[mi][ni][0]+bi0, C[mi][ni][1]+bi0);
            *reinterpret_cast<__half2*>(Oh + o0 + (size_t)8*NN) =
                __floats2half2_rn(C[mi][ni][2]+bi1, C[mi][ni][3]+bi1);
        }
    }
}

// ---------------- AB: A = relh2^T q, B = relw2^T q  (per b,h; fp32 out + abc bias) ----------------
__global__ __launch_bounds__(128) void ab_kernel(){
    __shared__ uint4 sm[1024];   // relh 0..256u, relw 256..512u, q 512..1024u
    const uint32_t sbase = (uint32_t)__cvta_generic_to_shared(sm);
    const int tid = threadIdx.x, lane = tid & 31, warp = tid >> 5;
    const int b = blockIdx.z, h = blockIdx.y, n0 = blockIdx.x * 64;

    #pragma unroll
    for (int s = 0; s < 4; s++){
        int idx = tid + s*128;
        int sel = idx >> 8, j = idx & 255;
        int r = j >> 2, u = j & 3;
        const __half* src = (sel ? g_rw2 : g_rh2) + (size_t)(h*64 + r)*32 + u*8;
        cp16(sbase + (uint32_t)(sel*256 + r*4 + (u ^ (r&3)))*16u, src);
    }
    #pragma unroll
    for (int s = 0; s < 4; s++){
        int idx = tid + s*128;
        int r = idx >> 3, u = idx & 7;
        cp16(sbase + (uint32_t)(512 + r*8 + (u ^ (r&7)))*16u,
             g_qh + ((size_t)b*NC + h*ND + r)*NN + n0 + u*8);
    }
    cp_commit(); cp_wait<0>(); __syncthreads();

    float accA[2][2][4], accB[2][2][4];
    #pragma unroll
    for (int a=0;a<2;a++)
        #pragma unroll
        for (int bb=0;bb<2;bb++)
            #pragma unroll
            for (int c=0;c<4;c++){ accA[a][bb][c]=0.f; accB[a][bb][c]=0.f; }

    #pragma unroll
    for (int k16 = 0; k16 < 4; k16++){
        uint32_t bF[2][2];
        int brow = k16*16 + (lane & 15);
        #pragma unroll
        for (int nt = 0; nt < 2; nt++){
            int bu = warp*2 + nt;
            ldsm2t(bF[nt], sbase + (uint32_t)(512 + brow*8 + (bu ^ (brow&7)))*16u);
        }
        int arow = k16*16 + (lane & 7) + ((lane >> 4) << 3);
        #pragma unroll
        for (int mt = 0; mt < 2; mt++){
            int au = mt*2 + ((lane >> 3) & 1);
            uint32_t aH[4], aW[4];
            ldsm4t(aH, sbase + (uint32_t)(arow*4 + (au ^ (arow&3)))*16u);
            ldsm4t(aW, sbase + (uint32_t)(256 + arow*4 + (au ^ (arow&3)))*16u);
            #pragma unroll
            for (int nt = 0; nt < 2; nt++){
                mma_f16(accA[mt][nt], aH, bF[nt]);
                mma_f16(accB[mt][nt], aW, bF[nt]);
            }
        }
    }
    #pragma unroll
    for (int mt = 0; mt < 2; mt++){
        int hc0 = mt*16 + (lane >> 2);
        float ac0 = g_abc[h*32 + hc0],       ac1 = g_abc[h*32 + hc0 + 8];
        float bc0 = g_abc[256 + h*32 + hc0], bc1 = g_abc[256 + h*32 + hc0 + 8];
        #pragma unroll
        for (int nt = 0; nt < 2; nt++){
            int n = n0 + warp*16 + nt*8 + (lane&3)*2;
            size_t rA = (size_t)b*512 + h*32 + hc0;
            float2 v;
            v.x = accA[mt][nt][0]+ac0; v.y = accA[mt][nt][1]+ac0;
            *reinterpret_cast<float2*>(g_ab + rA*NN + n) = v;
            v.x = accA[mt][nt][2]+ac1; v.y = accA[mt][nt][3]+ac1;
            *reinterpret_cast<float2*>(g_ab + (rA+8)*NN + n) = v;
            size_t rB = rA + 256;
            v.x = accB[mt][nt][0]+bc0; v.y = accB[mt][nt][1]+bc0;
            *reinterpret_cast<float2*>(g_ab + rB*NN + n) = v;
            v.x = accB[mt][nt][2]+bc1; v.y = accB[mt][nt][3]+bc1;
            *reinterpret_cast<float2*>(g_ab + (rB+8)*NN + n) = v;
        }
    }
}

// ---------------- attention: K=64 QK + A/B position terms, log2-domain online max ----------------
// smem units(16B): Q [0,1024): r*16+(u^(r&7)); K 1024+buf*512+r*8+(u^(r&7));
// V 2048+buf*512+r*8+(u^(r&7)); A 3072+buf*640 + hc*17+u; B +544 + wi*17+u. 4352u = 68KB.
__global__ __launch_bounds__(256, 2) void attn_mma_kernel(const float* __restrict__ x,
                                                          float* __restrict__ out)
{
    extern __shared__ uint4 smemraw[];
    const uint32_t sbase = (uint32_t)__cvta_generic_to_shared(smemraw);
    float* smf = reinterpret_cast<float*>(smemraw);
    char*  smc = reinterpret_cast<char*>(smemraw);
    const int tid = threadIdx.x, lane = tid & 31, warp = tid >> 5;
    const int wm = warp >> 1, wn = warp & 1;
    const int b = blockIdx.z, h = blockIdx.y;
    const int i0 = blockIdx.x * 128;
    const size_t qoff = ((size_t)b*NC + h*ND)*NN;
    const float* pA = g_ab + ((size_t)b*512 + h*32)*NN;
    const float* pB = g_ab + ((size_t)b*512 + 256 + h*32 + (i0 >> 5))*NN;

    auto loadQ = [&](){
        #pragma unroll
        for (int s = 0; s < 4; s++){
            int idx = tid + s*256;
            int r = idx >> 4, u = idx & 15;
            cp16(sbase + (uint32_t)(r*16 + (u ^ (r&7)))*16u,
                 g_qh + qoff + (size_t)r*NN + i0 + u*8);
        }
    };
    auto loadKV = [&](int jt, int buf){
        int j0 = jt * 64;
        #pragma unroll
        for (int s = 0; s < 2; s++){
            int idx = tid + (s<<8);
            int r = idx >> 3, u = idx & 7;
            cp16(sbase + (uint32_t)(1024 + buf*512 + r*8 + (u ^ (r&7)))*16u,
                 g_kh + qoff + (size_t)r*NN + j0 + u*8);
        }
        #pragma unroll
        for (int s = 0; s < 2; s++){
            int idx = tid + (s<<8);
            int r = idx >> 3, u = idx & 7;
            cp16(sbase + (uint32_t)(2048 + buf*512 + r*8 + (u ^ (r&7)))*16u,
                 g_vh + qoff + (size_t)r*NN + j0 + u*8);
        }
        #pragma unroll
        for (int s = 0; s < 2; s++){
            int idx = tid + (s<<8);
            int r = idx >> 4, u = idx & 15;     // r<32
            cp16(sbase + (uint32_t)(3072 + buf*640 + r*17 + u)*16u,
                 pA + (size_t)r*NN + j0 + u*4);
        }
        if (tid < 64){
            int r = tid >> 4, u = tid & 15;     // r<4
            cp16(sbase + (uint32_t)(3072 + buf*640 + 544 + r*17 + u)*16u,
                 pB + (size_t)r*NN + j0 + u*4);
        }
    };

    float Oc[2][8][4];
    #pragma unroll
    for (int a=0;a<2;a++)
        #pragma unroll
        for (int bb=0;bb<8;bb++)
            #pragma unroll
            for (int c=0;c<4;c++) Oc[a][bb][c]=0.f;
    float rs[2][2] = {{0.f,0.f},{0.f,0.f}};
    float mr[2][2] = {{-1e30f,-1e30f},{-1e30f,-1e30f}};

    loadQ(); loadKV(0, 0); cp_commit();

    for (int jt = 0; jt < 16; jt++){
        if (jt < 15){ loadKV(jt+1, (jt+1)&1); cp_commit(); cp_wait<1>(); }
        else        { cp_wait<0>(); }
        __syncthreads();
        int buf = jt & 1;

        // ---- S = q^T k (k=64, 4 k16 steps) ----
        float S[2][4][4];
        #pragma unroll
        for (int a=0;a<2;a++)
            #pragma unroll
            for (int bb=0;bb<4;bb++)
                #pragma unroll
                for (int c=0;c<4;c++) S[a][bb][c]=0.f;

        #pragma unroll
        for (int k16 = 0; k16 < 4; k16++){
            uint32_t aH[2][4], bH[4][2];
            int arow = k16*16 + (lane & 7) + ((lane >> 4) << 3);
            #pragma unroll
            for (int mi = 0; mi < 2; mi++){
                int au = wm*4 + mi*2 + ((lane >> 3) & 1);
                ldsm4t(aH[mi], sbase + (uint32_t)(arow*16 + (au ^ (arow&7)))*16u);
            }
            int brow = k16*16 + (lane & 15);
            #pragma unroll
            for (int ni = 0; ni < 4; ni++){
                int bu = wn*4 + ni;
                ldsm2t(bH[ni], sbase + (uint32_t)(1024 + buf*512 + brow*8 + (bu ^ (brow&7)))*16u);
            }
            #pragma unroll
            for (int mi = 0; mi < 2; mi++)
                #pragma unroll
                for (int ni = 0; ni < 4; ni++)
                    mma_f16(S[mi][ni], aH[mi], bH[ni]);
        }

        // ---- add position terms: S += A[hc(i), j] + B[w(i), j] (staged fp32 in smem) ----
        {
            uint32_t abase = (uint32_t)(3072 + buf*640)*16u;
            uint32_t bbase = abase + 544u*16u;
            #pragma unroll
            for (int mi = 0; mi < 2; mi++){
                int rL = wm*32 + mi*16 + (lane >> 2);
                int hcL = rL & 31, wiL = rL >> 5;
                int hcH = (rL + 8) & 31, wiH = (rL + 8) >> 5;
                #pragma unroll
                for (int ni = 0; ni < 4; ni++){
                    int jf = wn*32 + ni*8 + (lane & 3)*2;
                    float2 aL = *reinterpret_cast<float2*>(smc + abase + hcL*272 + jf*4);
                    float2 bL = *reinterpret_cast<float2*>(smc + bbase + wiL*272 + jf*4);
                    float2 aH = *reinterpret_cast<float2*>(smc + abase + hcH*272 + jf*4);
                    float2 bV = *reinterpret_cast<float2*>(smc + bbase + wiH*272 + jf*4);
                    S[mi][ni][0] += aL.x + bL.x;
                    S[mi][ni][1] += aL.y + bL.y;
                    S[mi][ni][2] += aH.x + bV.x;
                    S[mi][ni][3] += aH.y + bV.y;
                }
            }
        }

        // ---- online softmax in log2 domain: P = 2^(S - m) ----
        #pragma unroll
        for (int mi = 0; mi < 2; mi++){
            float t0 = -1e30f, t1 = -1e30f;
            #pragma unroll
            for (int ni = 0; ni < 4; ni++){
                t0 = fmaxf(t0, fmaxf(S[mi][ni][0], S[mi][ni][1]));
                t1 = fmaxf(t1, fmaxf(S[mi][ni][2], S[mi][ni][3]));
            }
            #pragma unroll
            for (int off = 1; off < 4; off <<= 1){
                t0 = fmaxf(t0, __shfl_xor_sync(0xffffffffu, t0, off));
                t1 = fmaxf(t1, __shfl_xor_sync(0xffffffffu, t1, off));
            }
            float nm0 = fmaxf(mr[mi][0], t0), nm1 = fmaxf(mr[mi][1], t1);
            float sc0 = ex2f(mr[mi][0] - nm0), sc1 = ex2f(mr[mi][1] - nm1);
            mr[mi][0] = nm0; mr[mi][1] = nm1;
            float ps0 = 0.f, ps1 = 0.f;
            #pragma unroll
            for (int ni = 0; ni < 4; ni++){
                S[mi][ni][0] = ex2f(S[mi][ni][0] - nm0);
                S[mi][ni][1] = ex2f(S[mi][ni][1] - nm0);
                S[mi][ni][2] = ex2f(S[mi][ni][2] - nm1);
                S[mi][ni][3] = ex2f(S[mi][ni][3] - nm1);
                ps0 += S[mi][ni][0] + S[mi][ni][1];
                ps1 += S[mi][ni][2] + S[mi][ni][3];
            }
            rs[mi][0] = rs[mi][0]*sc0 + ps0;
            rs[mi][1] = rs[mi][1]*sc1 + ps1;
            #pragma unroll
            for (int nd = 0; nd < 8; nd++){
                Oc[mi][nd][0] *= sc0; Oc[mi][nd][1] *= sc0;
                Oc[mi][nd][2] *= sc1; Oc[mi][nd][3] *= sc1;
            }
        }

        // ---- O += P V^T ----
        #pragma unroll
        for (int kt = 0; kt < 2; kt++){
            uint32_t pF[2][4];
            #pragma unroll
            for (int mi = 0; mi < 2; mi++){
                pF[mi][0] = packh2(S[mi][2*kt  ][0], S[mi][2*kt  ][1]);
                pF[mi][1] = packh2(S[mi][2*kt  ][2], S[mi][2*kt  ][3]);
                pF[mi][2] = packh2(S[mi][2*kt+1][0], S[mi][2*kt+1][1]);
                pF[mi][3] = packh2(S[mi][2*kt+1][2], S[mi][2*kt+1][3]);
            }
            #pragma unroll
            for (int nd = 0; nd < 8; nd++){
                int vrow = nd*8 + (lane & 7);
                int vu = wn*4 + kt*2 + ((lane >> 3) & 1);
                uint32_t vF[2];
                ldsm2(vF, sbase + (uint32_t)(2048 + buf*512 + vrow*8 + (vu ^ (vrow&7)))*16u);
                #pragma unroll
                for (int mi = 0; mi < 2; mi++)
                    mma_f16(Oc[mi][nd], pF[mi], vF);
            }
        }
        __syncthreads();
    }

    // ---- cross-warp combine (log2-domain max reconciliation), normalize, +x, store ----
    float* Os = smf;
    float* rsum_s = smf + 128*65;
    float* mmax_s = rsum_s + 128;
    #pragma unroll
    for (int off = 1; off < 4; off <<= 1)
        #pragma unroll
        for (int mi = 0; mi < 2; mi++){
            rs[mi][0] += __shfl_xor_sync(0xffffffffu, rs[mi][0], off);
            rs[mi][1] += __shfl_xor_sync(0xffffffffu, rs[mi][1], off);
        }
    if (wn == 0){
        #pragma unroll
        for (int mi = 0; mi < 2; mi++){
            int ib = wm*32 + mi*16 + (lane >> 2);
            #pragma unroll
            for (int nd = 0; nd < 8; nd++){
                int dd = nd*8 + (lane & 3)*2;
                Os[ib*65 + dd]       = Oc[mi][nd][0];
                Os[ib*65 + dd + 1]   = Oc[mi][nd][1];
                Os[(ib+8)*65 + dd]   = Oc[mi][nd][2];
                Os[(ib+8)*65 + dd+1] = Oc[mi][nd][3];
            }
            if ((lane & 3) == 0){
                rsum_s[ib]   = rs[mi][0]; rsum_s[ib+8] = rs[mi][1];
                mmax_s[ib]   = mr[mi][0]; mmax_s[ib+8] = mr[mi][1];
            }
        }
    }
    __syncthreads();
    if (wn == 1){
        #pragma unroll
        for (int mi = 0; mi < 2; mi++){
            int ib = wm*32 + mi*16 + (lane >> 2);
            float m0a = mmax_s[ib], m0b = mmax_s[ib+8];
            float Ma = fmaxf(m0a, mr[mi][0]), Mb = fmaxf(m0b, mr[mi][1]);
            float s0a = ex2f(m0a - Ma), s1a = ex2f(mr[mi][0] - Ma);
            float s0b = ex2f(m0b - Mb), s1b = ex2f(mr[mi][1] - Mb);
            #pragma unroll
            for (int nd = 0; nd < 8; nd++){
                int dd = nd*8 + (lane & 3)*2;
                Os[ib*65 + dd]       = Os[ib*65 + dd]      *s0a + Oc[mi][nd][0]*s1a;
                Os[ib*65 + dd + 1]   = Os[ib*65 + dd + 1]  *s0a + Oc[mi][nd][1]*s1a;
                Os[(ib+8)*65 + dd]   = Os[(ib+8)*65 + dd]  *s0b + Oc[mi][nd][2]*s1b;
                Os[(ib+8)*65 + dd+1] = Os[(ib+8)*65 + dd+1]*s0b + Oc[mi][nd][3]*s1b;
            }
            if ((lane & 3) == 0){
                rsum_s[ib]   = rsum_s[ib]  *s0a + rs[mi][0]*s1a;
                rsum_s[ib+8] = rsum_s[ib+8]*s0b + rs[mi][1]*s1b;
            }
        }
    }
    __syncthreads();
    if (tid < 128) rsum_s[tid] = 1.0f / rsum_s[tid];
    __syncthreads();

    const float* xb = x + qoff;
    float* ob = out + qoff;
    #pragma unroll
    for (int s = 0; s < 32; s++){
        int idx = tid + s*256;
        int dd = idx >> 7, iL = idx & 127;
        ob[(size_t)dd*NN + i0 + iL] =
            Os[iL*65 + dd] * rsum_s[iL] + xb[(size_t)dd*NN + i0 + iL];
    }
}

extern "C" void kernel_launch(void* const* d_in, const int* in_sizes, int n_in,
                              void* d_out, int out_size) {
    (void)in_sizes; (void)n_in; (void)out_size;
    const float* x     = (const float*)d_in[0];
    const float* Wq    = (const float*)d_in[1];
    const float* bq    = (const float*)d_in[2];
    const float* Wk    = (const float*)d_in[3];
    const float* bk    = (const float*)d_in[4];
    const float* Wv    = (const float*)d_in[5];
    const float* bv    = (const float*)d_in[6];
    const float* rel_h = (const float*)d_in[7];
    const float* rel_w = (const float*)d_in[8];
    // d_in[9]/d_in[10] (reg_qk/reg_v) provably dead (sliced away by out[:, :head]).
    float* out = (float*)d_out;

    cudaFuncSetAttribute(qkv_mma_kernel,
        cudaFuncAttributeMaxDynamicSharedMemorySize, 32768);
    cudaFuncSetAttribute(attn_mma_kernel,
        cudaFuncAttributeMaxDynamicSharedMemorySize, 4352*16);

    cvt_all_kernel<<<(X4 + 3*W4 + 255)/256, 256>>>(x, Wq, Wk, Wv);
    relabc_kernel<<<66, 256>>>(rel_h, rel_w, bq);
    qkv_mma_kernel<<<dim3(NN/128, NC/128, 3*NB), 256, 32768>>>(bq, bk, bv);
    ab_kernel<<<dim3(NN/64, NH, NB), 128>>>();
    attn_mma_kernel<<<dim3(NN/128, NH, NB), 256, 4352*16>>>(x, out);
}

// round 17
// speedup vs baseline: 1.0858x; 1.0858x over previous
#include <cuda_runtime.h>
#include <cuda_fp16.h>
#include <cstdint>

#define NB 16
#define NC 512
#define NN 1024
#define NH 8
#define ND 64
#define LOG2E 1.4426950408889634f

// ---------------- scratch (device globals; allocation-free) ----------------
__device__ __align__(16) __half g_qh[(size_t)NB*NC*NN];
__device__ __align__(16) __half g_kh[(size_t)NB*NC*NN];   // scaled by log2e
__device__ __align__(16) __half g_vh[(size_t)NB*NC*NN];
__device__ __align__(16) __half g_xh[(size_t)NB*NC*NN];
__device__ __align__(16) __half g_wh[(size_t)3*NC*NC];    // Wk segment scaled by log2e
__device__ __align__(16) __half g_rh2[8*64*32];           // rel_h * log2e, [h][d][hc]
__device__ __align__(16) __half g_rw2[8*64*32];           // rel_w * log2e, [h][d][w]
__device__ __align__(16) float  g_abc[512];               // rel^T bq * log2e
__device__ __align__(16) __half g_ab[(size_t)NB*512*NN];  // fp16: rows 0..255 A(h*32+hc), 256..511 B(h*32+w)

// ---------------- helpers ----------------
__device__ __forceinline__ void cp16(uint32_t dst, const void* src){
    asm volatile("cp.async.cg.shared.global [%0], [%1], 16;" :: "r"(dst), "l"(src));
}
__device__ __forceinline__ void cp_commit(){ asm volatile("cp.async.commit_group;"); }
template<int N> __device__ __forceinline__ void cp_wait(){
    asm volatile("cp.async.wait_group %0;" :: "n"(N));
}
__device__ __forceinline__ void ldsm4(uint32_t r[4], uint32_t a){
    asm volatile("ldmatrix.sync.aligned.m8n8.x4.shared.b16 {%0,%1,%2,%3},[%4];"
        : "=r"(r[0]),"=r"(r[1]),"=r"(r[2]),"=r"(r[3]) : "r"(a));
}
__device__ __forceinline__ void ldsm4t(uint32_t r[4], uint32_t a){
    asm volatile("ldmatrix.sync.aligned.m8n8.x4.trans.shared.b16 {%0,%1,%2,%3},[%4];"
        : "=r"(r[0]),"=r"(r[1]),"=r"(r[2]),"=r"(r[3]) : "r"(a));
}
__device__ __forceinline__ void ldsm2t(uint32_t r[2], uint32_t a){
    asm volatile("ldmatrix.sync.aligned.m8n8.x2.trans.shared.b16 {%0,%1},[%2];"
        : "=r"(r[0]),"=r"(r[1]) : "r"(a));
}
__device__ __forceinline__ void mma_f16(float* c, const uint32_t* a, const uint32_t* b){
    asm volatile("mma.sync.aligned.m16n8k16.row.col.f32.f16.f16.f32 "
        "{%0,%1,%2,%3},{%4,%5,%6,%7},{%8,%9},{%0,%1,%2,%3};"
        : "+f"(c[0]),"+f"(c[1]),"+f"(c[2]),"+f"(c[3])
        : "r"(a[0]),"r"(a[1]),"r"(a[2]),"r"(a[3]),"r"(b[0]),"r"(b[1]));
}
__device__ __forceinline__ uint32_t packh2(float x, float y){
    __half2 t = __floats2half2_rn(x, y);
    return *reinterpret_cast<uint32_t*>(&t);
}
__device__ __forceinline__ float ex2f(float x){
    float y; asm("ex2.approx.ftz.f32 %0,%1;" : "=f"(y) : "f"(x)); return y;
}

// ---------------- fused convert fp32 -> fp16 (x + Wq + Wk*log2e + Wv) ----------------
#define X4 2097152
#define W4 65536
__global__ void cvt_all_kernel(const float* __restrict__ x,
                               const float* __restrict__ Wq,
                               const float* __restrict__ Wk,
                               const float* __restrict__ Wv){
    int i = blockIdx.x * blockDim.x + threadIdx.x;
    const float* src; __half* dst; float sc = 1.f; int li;
    if (i < X4){ src = x; dst = g_xh; li = i; }
    else {
        int j = i - X4;
        int seg = j / W4; li = j - seg*W4;
        src = (seg==0) ? Wq : (seg==1) ? Wk : Wv;
        dst = g_wh + (size_t)seg*W4*4;
        if (seg == 1) sc = LOG2E;
    }
    float4 v = reinterpret_cast<const float4*>(src)[li];
    __half2* d2 = reinterpret_cast<__half2*>(dst + (size_t)4*li);
    d2[0] = __floats2half2_rn(v.x*sc, v.y*sc);
    d2[1] = __floats2half2_rn(v.z*sc, v.w*sc);
}

// rel -> fp16 scaled, plus abc[row] = rel^T bq * log2e
__global__ void relabc_kernel(const float* __restrict__ rel_h,
                              const float* __restrict__ rel_w,
                              const float* __restrict__ bq){
    int idx = blockIdx.x * blockDim.x + threadIdx.x;
    if (idx < 16384){
        g_rh2[idx] = __float2half(rel_h[idx]*LOG2E);
        g_rw2[idx] = __float2half(rel_w[idx]*LOG2E);
    } else if (idx < 16896){
        int row = idx - 16384;
        int sel = row >> 8, rr = row & 255;
        int h = rr >> 5, c = rr & 31;
        const float* rel = sel ? rel_w : rel_h;
        float acc = 0.f;
        #pragma unroll 8
        for (int d = 0; d < 64; d++)
            acc += rel[(h*64 + d)*32 + c] * bq[h*64 + d];
        g_abc[row] = acc * LOG2E;
    }
}

// ---------------- QKV GEMM (unchanged R14) ----------------
__global__ __launch_bounds__(256) void qkv_mma_kernel(
    const float* __restrict__ bq, const float* __restrict__ bk,
    const float* __restrict__ bv)
{
    extern __shared__ uint4 smemraw[];
    const uint32_t sbase = (uint32_t)__cvta_generic_to_shared(smemraw);
    const int tid = threadIdx.x, lane = tid & 31, warp = tid >> 5;
    const int wm = warp >> 2, wn = warp & 3;
    const int which = blockIdx.z % 3;
    const int b = blockIdx.z / 3;
    const int oT = blockIdx.y * 128, nT = blockIdx.x * 128;

    const __half* Wh = g_wh + (size_t)which*NC*NC;
    const __half* Xh = g_xh + (size_t)b*NC*NN;
    const float* bias = (which==0) ? bq : (which==1) ? bk : bv;
    __half* Oh = (which==0) ? g_qh : (which==1) ? g_kh : g_vh;
    const float bsc = (which==1) ? LOG2E : 1.f;

    auto aAddr = [&](int buf,int row,int u)->uint32_t{
        return sbase + (uint32_t)(buf*512 + row*4 + (u ^ ((row>>1)&3)))*16u; };
    auto bAddr = [&](int buf,int row,int u)->uint32_t{
        return sbase + (uint32_t)(1024 + buf*512 + row*16 + (u ^ (row&7)))*16u; };

    auto issue = [&](int ct, int buf){
        #pragma unroll
        for (int s = 0; s < 2; s++){
            int idx = tid + (s<<8); int row = idx >> 2, u = idx & 3;
            cp16(aAddr(buf,row,u), Wh + (size_t)(oT+row)*NC + ct + u*8);
        }
        #pragma unroll
        for (int s = 0; s < 2; s++){
            int idx = tid + (s<<8); int row = idx >> 4, u = idx & 15;
            cp16(bAddr(buf,row,u), Xh + (size_t)(ct+row)*NN + nT + u*8);
        }
    };

    float C[4][4][4];
    #pragma unroll
    for (int a=0;a<4;a++)
        #pragma unroll
        for (int bb=0;bb<4;bb++)
            #pragma unroll
            for (int c=0;c<4;c++) C[a][bb][c]=0.f;

    issue(0, 0); cp_commit();
    for (int it = 0; it < 16; it++){
        if (it < 15){ issue((it+1)*32, (it+1)&1); cp_commit(); cp_wait<1>(); }
        else        { cp_wait<0>(); }
        __syncthreads();
        int buf = it & 1;
        #pragma unroll
        for (int k16 = 0; k16 < 2; k16++){
            int kk = k16 << 4;
            uint32_t ah[4][4], bh[4][2];
            #pragma unroll
            for (int mi = 0; mi < 4; mi++){
                int row = wm*64 + mi*16 + (lane & 15);
                ldsm4(ah[mi], aAddr(buf,row,(kk>>3)+(lane>>4)));
            }
            #pragma unroll
            for (int ni = 0; ni < 4; ni++)
                ldsm2t(bh[ni], bAddr(buf, kk + (lane & 15), wn*4 + ni));
            #pragma unroll
            for (int mi = 0; mi < 4; mi++)
                #pragma unroll
                for (int ni = 0; ni < 4; ni++)
                    mma_f16(C[mi][ni], ah[mi], bh[ni]);
        }
        __syncthreads();
    }
    #pragma unroll
    for (int mi = 0; mi < 4; mi++){
        int r0 = oT + wm*64 + mi*16 + (lane >> 2);
        float bi0 = bias[r0]*bsc, bi1 = bias[r0 + 8]*bsc;
        #pragma unroll
        for (int ni = 0; ni < 4; ni++){
            int c0 = nT + wn*32 + ni*8 + (lane & 3)*2;
            size_t o0 = ((size_t)b*NC + r0)*NN + c0;
            *reinterpret_cast<__half2*>(Oh + o0) =
                __floats2half2_rn(C[mi][ni][0]+bi0, C[mi][ni][1]+bi0);
            *reinterpret_cast<__half2*>(Oh + o0 + (size_t)8*NN) =
                __floats2half2_rn(C[mi][ni][2]+bi1, C[mi][ni][3]+bi1);
        }
    }
}

// ---------------- AB: A = relh2^T q, B = relw2^T q  (per b,h; fp16 out + abc bias) ----------------
__global__ __launch_bounds__(128) void ab_kernel(){
    __shared__ uint4 sm[1024];   // relh 0..256u, relw 256..512u, q 512..1024u
    const uint32_t sbase = (uint32_t)__cvta_generic_to_shared(sm);
    const int tid = threadIdx.x, lane = tid & 31, warp = tid >> 5;
    const int b = blockIdx.z, h = blockIdx.y, n0 = blockIdx.x * 64;

    #pragma unroll
    for (int s = 0; s < 4; s++){
        int idx = tid + s*128;
        int sel = idx >> 8, j = idx & 255;
        int r = j >> 2, u = j & 3;
        const __half* src = (sel ? g_rw2 : g_rh2) + (size_t)(h*64 + r)*32 + u*8;
        cp16(sbase + (uint32_t)(sel*256 + r*4 + (u ^ (r&3)))*16u, src);
    }
    #pragma unroll
    for (int s = 0; s < 4; s++){
        int idx = tid + s*128;
        int r = idx >> 3, u = idx & 7;
        cp16(sbase + (uint32_t)(512 + r*8 + (u ^ (r&7)))*16u,
             g_qh + ((size_t)b*NC + h*ND + r)*NN + n0 + u*8);
    }
    cp_commit(); cp_wait<0>(); __syncthreads();

    float accA[2][2][4], accB[2][2][4];
    #pragma unroll
    for (int a=0;a<2;a++)
        #pragma unroll
        for (int bb=0;bb<2;bb++)
            #pragma unroll
            for (int c=0;c<4;c++){ accA[a][bb][c]=0.f; accB[a][bb][c]=0.f; }

    #pragma unroll
    for (int k16 = 0; k16 < 4; k16++){
        uint32_t bF[2][2];
        int brow = k16*16 + (lane & 15);
        #pragma unroll
        for (int nt = 0; nt < 2; nt++){
            int bu = warp*2 + nt;
            ldsm2t(bF[nt], sbase + (uint32_t)(512 + brow*8 + (bu ^ (brow&7)))*16u);
        }
        int arow = k16*16 + (lane & 7) + ((lane >> 4) << 3);
        #pragma unroll
        for (int mt = 0; mt < 2; mt++){
            int au = mt*2 + ((lane >> 3) & 1);
            uint32_t aH[4], aW[4];
            ldsm4t(aH, sbase + (uint32_t)(arow*4 + (au ^ (arow&3)))*16u);
            ldsm4t(aW, sbase + (uint32_t)(256 + arow*4 + (au ^ (arow&3)))*16u);
            #pragma unroll
            for (int nt = 0; nt < 2; nt++){
                mma_f16(accA[mt][nt], aH, bF[nt]);
                mma_f16(accB[mt][nt], aW, bF[nt]);
            }
        }
    }
    #pragma unroll
    for (int mt = 0; mt < 2; mt++){
        int hc0 = mt*16 + (lane >> 2);
        float ac0 = g_abc[h*32 + hc0],       ac1 = g_abc[h*32 + hc0 + 8];
        float bc0 = g_abc[256 + h*32 + hc0], bc1 = g_abc[256 + h*32 + hc0 + 8];
        #pragma unroll
        for (int nt = 0; nt < 2; nt++){
            int n = n0 + warp*16 + nt*8 + (lane&3)*2;
            size_t rA = (size_t)b*512 + h*32 + hc0;
            *reinterpret_cast<__half2*>(g_ab + rA*NN + n) =
                __floats2half2_rn(accA[mt][nt][0]+ac0, accA[mt][nt][1]+ac0);
            *reinterpret_cast<__half2*>(g_ab + (rA+8)*NN + n) =
                __floats2half2_rn(accA[mt][nt][2]+ac1, accA[mt][nt][3]+ac1);
            size_t rB = rA + 256;
            *reinterpret_cast<__half2*>(g_ab + rB*NN + n) =
                __floats2half2_rn(accB[mt][nt][0]+bc0, accB[mt][nt][1]+bc0);
            *reinterpret_cast<__half2*>(g_ab + (rB+8)*NN + n) =
                __floats2half2_rn(accB[mt][nt][2]+bc1, accB[mt][nt][3]+bc1);
        }
    }
}

// ---------------- attention: K=64 QK + fp16 A/B position adds, log2-domain online max ----------------
// smem units(16B): Q [0,1024): r*16+(u^(r&7)); K 1024+buf*512+r*8+(u^(r&7));
// V 2048+buf*512+r*8+(u^(r&7)); AB base 3072+buf*324: A r*9+u (32 rows), B +288 r*9+u (4 rows).
// Total 3720 units = 59520 B -> 2 CTAs/SM.
__global__ __launch_bounds__(256, 2) void attn_mma_kernel(const float* __restrict__ x,
                                                          float* __restrict__ out)
{
    extern __shared__ uint4 smemraw[];
    const uint32_t sbase = (uint32_t)__cvta_generic_to_shared(smemraw);
    float* smf = reinterpret_cast<float*>(smemraw);
    char*  smc = reinterpret_cast<char*>(smemraw);
    const int tid = threadIdx.x, lane = tid & 31, warp = tid >> 5;
    const int wm = warp >> 1, wn = warp & 1;
    const int b = blockIdx.z, h = blockIdx.y;
    const int i0 = blockIdx.x * 128;
    const size_t qoff = ((size_t)b*NC + h*ND)*NN;
    const __half* pA = g_ab + ((size_t)b*512 + h*32)*NN;
    const __half* pB = g_ab + ((size_t)b*512 + 256 + h*32 + (i0 >> 5))*NN;

    auto loadQ = [&](){
        #pragma unroll
        for (int s = 0; s < 4; s++){
            int idx = tid + s*256;
            int r = idx >> 4, u = idx & 15;
            cp16(sbase + (uint32_t)(r*16 + (u ^ (r&7)))*16u,
                 g_qh + qoff + (size_t)r*NN + i0 + u*8);
        }
    };
    auto loadKV = [&](int jt, int buf){
        int j0 = jt * 64;
        #pragma unroll
        for (int s = 0; s < 2; s++){
            int idx = tid + (s<<8);
            int r = idx >> 3, u = idx & 7;
            cp16(sbase + (uint32_t)(1024 + buf*512 + r*8 + (u ^ (r&7)))*16u,
                 g_kh + qoff + (size_t)r*NN + j0 + u*8);
        }
        #pragma unroll
        for (int s = 0; s < 2; s++){
            int idx = tid + (s<<8);
            int r = idx >> 3, u = idx & 7;
            cp16(sbase + (uint32_t)(2048 + buf*512 + r*8 + (u ^ (r&7)))*16u,
                 g_vh + qoff + (size_t)r*NN + j0 + u*8);
        }
        if (tid < 256){   // A: 32 rows x 8 units (fp16)
            int r = tid >> 3, u = tid & 7;
            cp16(sbase + (uint32_t)(3072 + buf*324 + r*9 + u)*16u,
                 pA + (size_t)r*NN + j0 + u*8);
        }
        if (tid < 32){    // B: 4 rows x 8 units
            int r = tid >> 3, u = tid & 7;
            cp16(sbase + (uint32_t)(3072 + buf*324 + 288 + r*9 + u)*16u,
                 pB + (size_t)r*NN + j0 + u*8);
        }
    };

    float Oc[2][8][4];
    #pragma unroll
    for (int a=0;a<2;a++)
        #pragma unroll
        for (int bb=0;bb<8;bb++)
            #pragma unroll
            for (int c=0;c<4;c++) Oc[a][bb][c]=0.f;
    float rs[2][2] = {{0.f,0.f},{0.f,0.f}};
    float mr[2][2] = {{-1e30f,-1e30f},{-1e30f,-1e30f}};

    loadQ(); loadKV(0, 0); cp_commit();

    for (int jt = 0; jt < 16; jt++){
        if (jt < 15){ loadKV(jt+1, (jt+1)&1); cp_commit(); cp_wait<1>(); }
        else        { cp_wait<0>(); }
        __syncthreads();
        int buf = jt & 1;

        // ---- S = q^T k (k=64, 4 k16 steps; B-frags paired via ldsm4t) ----
        float S[2][4][4];
        #pragma unroll
        for (int a=0;a<2;a++)
            #pragma unroll
            for (int bb=0;bb<4;bb++)
                #pragma unroll
                for (int c=0;c<4;c++) S[a][bb][c]=0.f;

        #pragma unroll
        for (int k16 = 0; k16 < 4; k16++){
            uint32_t aH[2][4], bP[2][4];
            int arow = k16*16 + (lane & 7) + ((lane >> 4) << 3);
            #pragma unroll
            for (int mi = 0; mi < 2; mi++){
                int au = wm*4 + mi*2 + ((lane >> 3) & 1);
                ldsm4t(aH[mi], sbase + (uint32_t)(arow*16 + (au ^ (arow&7)))*16u);
            }
            int brow = k16*16 + (lane & 15);
            #pragma unroll
            for (int np = 0; np < 2; np++){
                int bu = wn*4 + np*2 + (lane >> 4);
                ldsm4t(bP[np], sbase + (uint32_t)(1024 + buf*512 + brow*8 + (bu ^ (brow&7)))*16u);
            }
            #pragma unroll
            for (int mi = 0; mi < 2; mi++){
                mma_f16(S[mi][0], aH[mi], bP[0]);
                mma_f16(S[mi][1], aH[mi], bP[0] + 2);
                mma_f16(S[mi][2], aH[mi], bP[1]);
                mma_f16(S[mi][3], aH[mi], bP[1] + 2);
            }
        }

        // ---- add position terms: S += A[hc(i), j] + B[w(i), j] (fp16 smem, half2) ----
        {
            const char* abse = smc + (size_t)(3072 + buf*324)*16;
            const char* bbse = abse + 288*16;
            __half2 bvv[4];
            #pragma unroll
            for (int ni = 0; ni < 4; ni++){
                int jf = wn*32 + ni*8 + (lane & 3)*2;
                bvv[ni] = *reinterpret_cast<const __half2*>(bbse + wm*144 + jf*2);
            }
            #pragma unroll
            for (int mi = 0; mi < 2; mi++){
                int hcL = mi*16 + (lane >> 2);
                #pragma unroll
                for (int ni = 0; ni < 4; ni++){
                    int jf = wn*32 + ni*8 + (lane & 3)*2;
                    __half2 aL = *reinterpret_cast<const __half2*>(abse + hcL*144 + jf*2);
                    __half2 aU = *reinterpret_cast<const __half2*>(abse + (hcL+8)*144 + jf*2);
                    float2 fL = __half22float2(__hadd2(aL, bvv[ni]));
                    float2 fU = __half22float2(__hadd2(aU, bvv[ni]));
                    S[mi][ni][0] += fL.x;
                    S[mi][ni][1] += fL.y;
                    S[mi][ni][2] += fU.x;
                    S[mi][ni][3] += fU.y;
                }
            }
        }

        // ---- online softmax in log2 domain: P = 2^(S - m) ----
        #pragma unroll
        for (int mi = 0; mi < 2; mi++){
            float t0 = -1e30f, t1 = -1e30f;
            #pragma unroll
            for (int ni = 0; ni < 4; ni++){
                t0 = fmaxf(t0, fmaxf(S[mi][ni][0], S[mi][ni][1]));
                t1 = fmaxf(t1, fmaxf(S[mi][ni][2], S[mi][ni][3]));
            }
            #pragma unroll
            for (int off = 1; off < 4; off <<= 1){
                t0 = fmaxf(t0, __shfl_xor_sync(0xffffffffu, t0, off));
                t1 = fmaxf(t1, __shfl_xor_sync(0xffffffffu, t1, off));
            }
            float nm0 = fmaxf(mr[mi][0], t0), nm1 = fmaxf(mr[mi][1], t1);
            float sc0 = ex2f(mr[mi][0] - nm0), sc1 = ex2f(mr[mi][1] - nm1);
            mr[mi][0] = nm0; mr[mi][1] = nm1;
            float ps0 = 0.f, ps1 = 0.f;
            #pragma unroll
            for (int ni = 0; ni < 4; ni++){
                S[mi][ni][0] = ex2f(S[mi][ni][0] - nm0);
                S[mi][ni][1] = ex2f(S[mi][ni][1] - nm0);
                S[mi][ni][2] = ex2f(S[mi][ni][2] - nm1);
                S[mi][ni][3] = ex2f(S[mi][ni][3] - nm1);
                ps0 += S[mi][ni][0] + S[mi][ni][1];
                ps1 += S[mi][ni][2] + S[mi][ni][3];
            }
            rs[mi][0] = rs[mi][0]*sc0 + ps0;
            rs[mi][1] = rs[mi][1]*sc1 + ps1;
            #pragma unroll
            for (int nd = 0; nd < 8; nd++){
                Oc[mi][nd][0] *= sc0; Oc[mi][nd][1] *= sc0;
                Oc[mi][nd][2] *= sc1; Oc[mi][nd][3] *= sc1;
            }
        }

        // ---- O += P V^T (V pairs via ldsm4) ----
        #pragma unroll
        for (int kt = 0; kt < 2; kt++){
            uint32_t pF[2][4];
            #pragma unroll
            for (int mi = 0; mi < 2; mi++){
                pF[mi][0] = packh2(S[mi][2*kt  ][0], S[mi][2*kt  ][1]);
                pF[mi][1] = packh2(S[mi][2*kt  ][2], S[mi][2*kt  ][3]);
                pF[mi][2] = packh2(S[mi][2*kt+1][0], S[mi][2*kt+1][1]);
                pF[mi][3] = packh2(S[mi][2*kt+1][2], S[mi][2*kt+1][3]);
            }
            #pragma unroll
            for (int ndp = 0; ndp < 4; ndp++){
                int vrow = (ndp*2 + (lane >> 4))*8 + (lane & 7);
                int vu = wn*4 + kt*2 + ((lane >> 3) & 1);
                uint32_t vP[4];
                ldsm4(vP, sbase + (uint32_t)(2048 + buf*512 + vrow*8 + (vu ^ (vrow&7)))*16u);
                #pragma unroll
                for (int mi = 0; mi < 2; mi++){
                    mma_f16(Oc[mi][2*ndp  ], pF[mi], vP);
                    mma_f16(Oc[mi][2*ndp+1], pF[mi], vP + 2);
                }
            }
        }
        __syncthreads();
    }

    // ---- cross-warp combine (log2-domain max reconciliation), normalize, +x, store ----
    float* Os = smf;
    float* rsum_s = smf + 128*65;
    float* mmax_s = rsum_s + 128;
    #pragma unroll
    for (int off = 1; off < 4; off <<= 1)
        #pragma unroll
        for (int mi = 0; mi < 2; mi++){
            rs[mi][0] += __shfl_xor_sync(0xffffffffu, rs[mi][0], off);
            rs[mi][1] += __shfl_xor_sync(0xffffffffu, rs[mi][1], off);
        }
    if (wn == 0){
        #pragma unroll
        for (int mi = 0; mi < 2; mi++){
            int ib = wm*32 + mi*16 + (lane >> 2);
            #pragma unroll
            for (int nd = 0; nd < 8; nd++){
                int dd = nd*8 + (lane & 3)*2;
                Os[ib*65 + dd]       = Oc[mi][nd][0];
                Os[ib*65 + dd + 1]   = Oc[mi][nd][1];
                Os[(ib+8)*65 + dd]   = Oc[mi][nd][2];
                Os[(ib+8)*65 + dd+1] = Oc[mi][nd][3];
            }
            if ((lane & 3) == 0){
                rsum_s[ib]   = rs[mi][0]; rsum_s[ib+8] = rs[mi][1];
                mmax_s[ib]   = mr[mi][0]; mmax_s[ib+8] = mr[mi][1];
            }
        }
    }
    __syncthreads();
    if (wn == 1){
        #pragma unroll
        for (int mi = 0; mi < 2; mi++){
            int ib = wm*32 + mi*16 + (lane >> 2);
            float m0a = mmax_s[ib], m0b = mmax_s[ib+8];
            float Ma = fmaxf(m0a, mr[mi][0]), Mb = fmaxf(m0b, mr[mi][1]);
            float s0a = ex2f(m0a - Ma), s1a = ex2f(mr[mi][0] - Ma);
            float s0b = ex2f(m0b - Mb), s1b = ex2f(mr[mi][1] - Mb);
            #pragma unroll
            for (int nd = 0; nd < 8; nd++){
                int dd = nd*8 + (lane & 3)*2;
                Os[ib*65 + dd]       = Os[ib*65 + dd]      *s0a + Oc[mi][nd][0]*s1a;
                Os[ib*65 + dd + 1]   = Os[ib*65 + dd + 1]  *s0a + Oc[mi][nd][1]*s1a;
                Os[(ib+8)*65 + dd]   = Os[(ib+8)*65 + dd]  *s0b + Oc[mi][nd][2]*s1b;
                Os[(ib+8)*65 + dd+1] = Os[(ib+8)*65 + dd+1]*s0b + Oc[mi][nd][3]*s1b;
            }
            if ((lane & 3) == 0){
                rsum_s[ib]   = rsum_s[ib]  *s0a + rs[mi][0]*s1a;
                rsum_s[ib+8] = rsum_s[ib+8]*s0b + rs[mi][1]*s1b;
            }
        }
    }
    __syncthreads();
    if (tid < 128) rsum_s[tid] = 1.0f / rsum_s[tid];
    __syncthreads();

    const float* xb = x + qoff;
    float* ob = out + qoff;
    #pragma unroll
    for (int s = 0; s < 32; s++){
        int idx = tid + s*256;
        int dd = idx >> 7, iL = idx & 127;
        ob[(size_t)dd*NN + i0 + iL] =
            Os[iL*65 + dd] * rsum_s[iL] + xb[(size_t)dd*NN + i0 + iL];
    }
}

extern "C" void kernel_launch(void* const* d_in, const int* in_sizes, int n_in,
                              void* d_out, int out_size) {
    (void)in_sizes; (void)n_in; (void)out_size;
    const float* x     = (const float*)d_in[0];
    const float* Wq    = (const float*)d_in[1];
    const float* bq    = (const float*)d_in[2];
    const float* Wk    = (const float*)d_in[3];
    const float* bk    = (const float*)d_in[4];
    const float* Wv    = (const float*)d_in[5];
    const float* bv    = (const float*)d_in[6];
    const float* rel_h = (const float*)d_in[7];
    const float* rel_w = (const float*)d_in[8];
    // d_in[9]/d_in[10] (reg_qk/reg_v) provably dead (sliced away by out[:, :head]).
    float* out = (float*)d_out;

    cudaFuncSetAttribute(qkv_mma_kernel,
        cudaFuncAttributeMaxDynamicSharedMemorySize, 32768);
    cudaFuncSetAttribute(attn_mma_kernel,
        cudaFuncAttributeMaxDynamicSharedMemorySize, 3720*16);

    cvt_all_kernel<<<(X4 + 3*W4 + 255)/256, 256>>>(x, Wq, Wk, Wv);
    relabc_kernel<<<66, 256>>>(rel_h, rel_w, bq);
    qkv_mma_kernel<<<dim3(NN/128, NC/128, 3*NB), 256, 32768>>>(bq, bk, bv);
    ab_kernel<<<dim3(NN/64, NH, NB), 128>>>();
    attn_mma_kernel<<<dim3(NN/128, NH, NB), 256, 3720*16>>>(x, out);
}